// round 3
// baseline (speedup 1.0000x reference)
#include <cuda_runtime.h>
#include <math.h>
#include <stdint.h>

#define N_TOT 32768
#define B_    8
#define NG_   4096
#define KNN_  3
#define IN_CH_ 32
#define HID_  64
#define M_    100
#define OUT_CH_ 16
#define NP_   800      // B*M pooled nodes
#define E_PPI_ 600

// ------------------------------ scratch (device globals; no allocs) ---------
__device__ float g_sq[N_TOT];
__device__ int   g_knn[N_TOT * 3];
__device__ float g_dn[N_TOT];
__device__ float g_wn[N_TOT * 3];
__device__ float g_Z[(size_t)N_TOT * 256];
__device__ float g_u0[(size_t)N_TOT * 64];
__device__ float g_u1[(size_t)N_TOT * 400];
__device__ float g_t1[(size_t)N_TOT * 200];
__device__ float g_t2[(size_t)N_TOT * 100];
__device__ float g_S [(size_t)N_TOT * 100];
__device__ float g_amean[B_ * HID_];
__device__ float g_rstd [B_ * HID_];
__device__ float g_xp[NP_ * IN_CH_];
__device__ float g_h [NP_ * HID_];
__device__ float g_y [NP_ * HID_];
__device__ int   g_knn2[NP_ * 3];

// ------------------------------ helpers -------------------------------------
__device__ __forceinline__ float selu_f(float x) {
    const float sc = 1.0507009873554804934193349852946f;
    const float al = 1.6732632423543772848170429916717f;
    return x > 0.f ? sc * x : sc * al * expm1f(x);
}

// ---- squared norms, mimicking XLA GPU row-reduce rounding -------------------
// C=32: one element per lane, shuffle tree offsets 16,8,4,2,1.
__global__ void sqnorm32_kernel(const float* __restrict__ x, float* __restrict__ sq, int n) {
    int i = blockIdx.x * blockDim.x + threadIdx.x;
    if (i >= n) return;
    const float* r = x + (size_t)i * 32;
    float p[32];
#pragma unroll
    for (int c = 0; c < 32; c++) p[c] = __fmul_rn(r[c], r[c]);
#pragma unroll
    for (int off = 16; off > 0; off >>= 1)
#pragma unroll
        for (int c = 0; c < 16; c++)
            if (c < off) p[c] = __fadd_rn(p[c], p[c + off]);
    sq[i] = p[0];
}

// C=64: float2 per lane (elements 2t, 2t+1 fma-chained), then tree 16..1.
__global__ void sqnorm64_kernel(const float* __restrict__ x, float* __restrict__ sq, int n) {
    int i = blockIdx.x * blockDim.x + threadIdx.x;
    if (i >= n) return;
    const float* r = x + (size_t)i * 64;
    float p[32];
#pragma unroll
    for (int t = 0; t < 32; t++) {
        float a = __fmaf_rn(r[2 * t], r[2 * t], 0.f);
        p[t] = __fmaf_rn(r[2 * t + 1], r[2 * t + 1], a);
    }
#pragma unroll
    for (int off = 16; off > 0; off >>= 1)
#pragma unroll
        for (int c = 0; c < 16; c++)
            if (c < off) p[c] = __fadd_rn(p[c], p[c + off]);
    sq[i] = p[0];
}

// ------------------------------ kNN (k=3, per graph) ------------------------
// Distance arithmetic mimics the reference: dot = sequential ascending-k FMA
// chain (cuBLAS SGEMM per-thread order); d = (sq_i + sq_j) - 2*dot with
// explicit non-contracted fp32 ops. Strict '<' ladder with ascending j
// reproduces jax.lax.top_k stability (lower index wins ties).
template<int C>
__global__ void knn_kernel(const float* __restrict__ x, const float* __restrict__ sq,
                           int* __restrict__ knn, int nper) {
    const int TJ = 128;
    int b  = blockIdx.y;
    int il = blockIdx.x * 128 + threadIdx.x;   // local node in graph
    int gi = b * nper + il;

    float xif[C];
    {
        const float4* xrow = (const float4*)(x + (size_t)gi * C);
#pragma unroll
        for (int q = 0; q < C / 4; q++) {
            float4 v = xrow[q];
            xif[4 * q + 0] = v.x; xif[4 * q + 1] = v.y;
            xif[4 * q + 2] = v.z; xif[4 * q + 3] = v.w;
        }
    }
    float sqi = sq[gi];

    float bd0 = 3.4e38f, bd1 = 3.4e38f, bd2 = 3.4e38f;
    int   bi0 = 0, bi1 = 0, bi2 = 0;

    __shared__ float4 xs[TJ * (C / 4)];
    __shared__ float  sqs[TJ];

    for (int j0 = 0; j0 < nper; j0 += TJ) {
        __syncthreads();
        const float4* src4 = (const float4*)(x + (size_t)(b * nper + j0) * C);
        for (int t = threadIdx.x; t < TJ * (C / 4); t += 128) xs[t] = src4[t];
        for (int t = threadIdx.x; t < TJ; t += 128) sqs[t] = sq[b * nper + j0 + t];
        __syncthreads();
#pragma unroll 4
        for (int jj = 0; jj < TJ; jj++) {
            float xj[C];
#pragma unroll
            for (int q = 0; q < C / 4; q++) {
                float4 v = xs[jj * (C / 4) + q];
                xj[4 * q + 0] = v.x; xj[4 * q + 1] = v.y;
                xj[4 * q + 2] = v.z; xj[4 * q + 3] = v.w;
            }
            // sequential ascending FMA chain (matches cublas k-order)
            float dot = 0.f;
#pragma unroll
            for (int c = 0; c < C; c++) dot = __fmaf_rn(xif[c], xj[c], dot);
            float t1 = __fadd_rn(sqi, sqs[jj]);
            float t2 = __fmul_rn(2.f, dot);
            float d  = __fsub_rn(t1, t2);
            int j = j0 + jj;
            if (j == il) continue;
            if (d < bd2) {
                if (d < bd0)      { bd2=bd1; bi2=bi1; bd1=bd0; bi1=bi0; bd0=d; bi0=j; }
                else if (d < bd1) { bd2=bd1; bi2=bi1; bd1=d;   bi1=j; }
                else              { bd2=d;   bi2=j; }
            }
        }
    }
    knn[gi * 3 + 0] = b * nper + bi0;
    knn[gi * 3 + 1] = b * nper + bi1;
    knn[gi * 3 + 2] = b * nper + bi2;
}

// ------------------------------ degree / edge normalization -----------------
__global__ void dn_kernel(const float* __restrict__ w, float* __restrict__ dn, int n) {
    int g = blockIdx.x * blockDim.x + threadIdx.x;
    if (g >= n) return;
    float d = w[3 * g] + w[3 * g + 1] + w[3 * g + 2];
    dn[g] = d > 0.f ? rsqrtf(fmaxf(d, 1e-12f)) : 0.f;
}

__global__ void wn_kernel(const float* __restrict__ w, const int* __restrict__ knn,
                          const float* __restrict__ dn, float* __restrict__ wn, int ne) {
    int e = blockIdx.x * blockDim.x + threadIdx.x;
    if (e >= ne) return;
    int g = e / 3;
    wn[e] = w[e] * dn[g] * dn[knn[e]];
}

// ------------------------------ copy into Z slice ---------------------------
__global__ void copy_slice_kernel(const float* __restrict__ src, float* __restrict__ Z,
                                  int Cq, int stride4, int total) {
    int idx = blockIdx.x * blockDim.x + threadIdx.x;
    if (idx >= total) return;
    int g = idx / Cq, q = idx % Cq;
    ((float4*)Z)[(size_t)g * stride4 + q] = ((const float4*)src)[(size_t)g * Cq + q];
}

// ------------------------------ Laplacian step -------------------------------
// out = alpha * ( -(w0*v[s0] + w1*v[s1] + w2*v[s2]) ) + beta * prev
__global__ void lap_kernel(const float* __restrict__ Zin, const float* __restrict__ Zprev,
                           float* __restrict__ Zout, int stride, int Cq,
                           float alpha, float beta,
                           const int* __restrict__ knn, const float* __restrict__ wn,
                           int total) {
    int idx = blockIdx.x * blockDim.x + threadIdx.x;
    if (idx >= total) return;
    int g = idx / Cq, q = idx % Cq;
    int s0 = knn[3 * g], s1 = knn[3 * g + 1], s2 = knn[3 * g + 2];
    float w0 = wn[3 * g], w1 = wn[3 * g + 1], w2 = wn[3 * g + 2];
    float4 a0 = ((const float4*)(Zin + (size_t)s0 * stride))[q];
    float4 a1 = ((const float4*)(Zin + (size_t)s1 * stride))[q];
    float4 a2 = ((const float4*)(Zin + (size_t)s2 * stride))[q];
    float4 r;
    r.x = alpha * (-(w0 * a0.x + w1 * a1.x + w2 * a2.x));
    r.y = alpha * (-(w0 * a0.y + w1 * a1.y + w2 * a2.y));
    r.z = alpha * (-(w0 * a0.z + w1 * a1.z + w2 * a2.z));
    r.w = alpha * (-(w0 * a0.w + w1 * a1.w + w2 * a2.w));
    if (beta != 0.f) {
        float4 p = ((const float4*)(Zprev + (size_t)g * stride))[q];
        r.x += beta * p.x; r.y += beta * p.y; r.z += beta * p.z; r.w += beta * p.w;
    }
    ((float4*)(Zout + (size_t)g * stride))[q] = r;
}

// ------------------------------ tiled GEMM + bias + act ---------------------
// C[M,N] = act(A[M,K] @ B[K,N] + bias), BM=BN=64, BK=16, 4x4 microtile.
template<int ACT>
__global__ void gemm_kernel(const float* __restrict__ A, const float* __restrict__ B,
                            const float* __restrict__ bias, float* __restrict__ C,
                            int K, int Ncols) {
    __shared__ float As[16][64];
    __shared__ float Bs[16][64];
    const int tid  = threadIdx.x;
    const int row0 = blockIdx.y * 64;
    const int col0 = blockIdx.x * 64;
    const int tx = tid & 15, ty = tid >> 4;
    float acc[4][4];
#pragma unroll
    for (int i = 0; i < 4; i++)
#pragma unroll
        for (int j = 0; j < 4; j++) acc[i][j] = 0.f;

    const int lin  = tid * 4;
    const int arow = lin >> 4, acol = lin & 15;
    const int brow = lin >> 6, bcol = lin & 63;

    for (int k0 = 0; k0 < K; k0 += 16) {
        float4 av = make_float4(0.f, 0.f, 0.f, 0.f);
        if (k0 + acol < K)
            av = *(const float4*)(A + (size_t)(row0 + arow) * K + k0 + acol);
        As[acol + 0][arow] = av.x; As[acol + 1][arow] = av.y;
        As[acol + 2][arow] = av.z; As[acol + 3][arow] = av.w;

        float4 bv = make_float4(0.f, 0.f, 0.f, 0.f);
        int gk = k0 + brow, gc = col0 + bcol;
        if (gk < K && gc < Ncols)
            bv = *(const float4*)(B + (size_t)gk * Ncols + gc);
        *(float4*)&Bs[brow][bcol] = bv;
        __syncthreads();
#pragma unroll
        for (int kk = 0; kk < 16; kk++) {
            float4 a = *(const float4*)&As[kk][ty * 4];
            float4 b = *(const float4*)&Bs[kk][tx * 4];
            float ar[4] = {a.x, a.y, a.z, a.w};
            float br[4] = {b.x, b.y, b.z, b.w};
#pragma unroll
            for (int i = 0; i < 4; i++)
#pragma unroll
                for (int j = 0; j < 4; j++) acc[i][j] += ar[i] * br[j];
        }
        __syncthreads();
    }
#pragma unroll
    for (int i = 0; i < 4; i++) {
        int row = row0 + ty * 4 + i;
#pragma unroll
        for (int j = 0; j < 4; j++) {
            int col = col0 + tx * 4 + j;
            if (col < Ncols) {
                float v = acc[i][j] + bias[col];
                if (ACT == 1) v = selu_f(v);
                C[(size_t)row * Ncols + col] = v;
            }
        }
    }
}

// ------------------------------ GraphNorm -----------------------------------
__global__ void gn_reduce_kernel(const float* __restrict__ u, const float* __restrict__ alpha,
                                 float* __restrict__ amean, float* __restrict__ rstd) {
    int b = blockIdx.x;
    int t = threadIdx.x;               // 256
    int c = t & 63, rg = t >> 6;
    float s = 0.f;
    for (int n = rg; n < NG_; n += 4) s += u[((size_t)(b * NG_ + n)) * 64 + c];
    __shared__ float sh[256];
    sh[t] = s;
    __syncthreads();
    __shared__ float smean[64];
    if (t < 64) {
        s = sh[t] + sh[t + 64] + sh[t + 128] + sh[t + 192];
        smean[t] = s * (1.f / NG_);
    }
    __syncthreads();
    float am = alpha[c] * smean[c];
    float s2 = 0.f;
    for (int n = rg; n < NG_; n += 4) {
        float v = u[((size_t)(b * NG_ + n)) * 64 + c] - am;
        s2 += v * v;
    }
    sh[t] = s2;
    __syncthreads();
    if (t < 64) {
        s2 = sh[t] + sh[t + 64] + sh[t + 128] + sh[t + 192];
        float var = s2 * (1.f / NG_);
        amean[b * 64 + t] = alpha[t] * smean[t];
        rstd [b * 64 + t] = rsqrtf(var + 1e-5f);
    }
}

__global__ void gn_norm_kernel(float* __restrict__ u, const float* __restrict__ gamma,
                               const float* __restrict__ beta, const float* __restrict__ amean,
                               const float* __restrict__ rstd) {
    int idx = blockIdx.x * blockDim.x + threadIdx.x;
    if (idx >= N_TOT * 64) return;
    int g = idx >> 6, c = idx & 63;
    int b = g >> 12;   // /4096
    float v = u[idx];
    u[idx] = gamma[c] * (v - amean[b * 64 + c]) * rstd[b * 64 + c] + beta[c];
}

// ------------------------------ softmax rows (width 100) --------------------
__global__ void softmax_kernel(const float* __restrict__ u, float* __restrict__ S) {
    int r = blockIdx.x * blockDim.x + threadIdx.x;
    if (r >= N_TOT) return;
    const float* row = u + (size_t)r * M_;
    float* so = S + (size_t)r * M_;
    float m = -3.4e38f;
    for (int i = 0; i < M_; i++) m = fmaxf(m, row[i]);
    float s = 0.f;
    for (int i = 0; i < M_; i++) { float e = expf(row[i] - m); so[i] = e; s += e; }
    float inv = 1.f / s;
    for (int i = 0; i < M_; i++) so[i] *= inv;
}

// ------------------------------ DiffPool pooling ----------------------------
// block (m=blockIdx.x, b=blockIdx.y), 128 threads
__global__ void pool_kernel(const float* __restrict__ S, const float* __restrict__ x,
                            float* __restrict__ xp) {
    int m = blockIdx.x, b = blockIdx.y;
    int t = threadIdx.x;
    float acc[32];
#pragma unroll
    for (int c = 0; c < 32; c++) acc[c] = 0.f;
    float ssum = 0.f;
    for (int n = t; n < NG_; n += 128) {
        float s = S[((size_t)(b * NG_ + n)) * M_ + m];
        ssum += s;
        const float4* xr = (const float4*)(x + (size_t)(b * NG_ + n) * 32);
#pragma unroll
        for (int q = 0; q < 8; q++) {
            float4 v = xr[q];
            acc[4 * q + 0] += s * v.x; acc[4 * q + 1] += s * v.y;
            acc[4 * q + 2] += s * v.z; acc[4 * q + 3] += s * v.w;
        }
    }
#pragma unroll
    for (int c = 0; c < 32; c++) {
        float v = acc[c];
        for (int off = 16; off > 0; off >>= 1) v += __shfl_down_sync(0xffffffffu, v, off);
        acc[c] = v;
    }
    { float v = ssum; for (int off = 16; off > 0; off >>= 1) v += __shfl_down_sync(0xffffffffu, v, off); ssum = v; }
    __shared__ float red[4][33];
    int lane = t & 31, w = t >> 5;
    if (lane == 0) { for (int c = 0; c < 32; c++) red[w][c] = acc[c]; red[w][32] = ssum; }
    __syncthreads();
    if (t < 33) { red[0][t] = red[0][t] + red[1][t] + red[2][t] + red[3][t]; }
    __syncthreads();
    if (t < 32) xp[((size_t)(b * M_ + m)) * 32 + t] = red[0][t] / red[0][32];
}

// ------------------------------ zero-init -----------------------------------
__global__ void zero2_kernel(float* a, float* b, int n) {
    int i = blockIdx.x * blockDim.x + threadIdx.x;
    if (i < n) { a[i] = 0.f; b[i] = 0.f; }
}

// ------------------------------ PPI edge conv -------------------------------
// block: 4 edges x 64 out-channels
__global__ void ppi_conv_kernel(const float* __restrict__ xp, const int* __restrict__ connect,
                                const float* __restrict__ W2, const float* __restrict__ b2,
                                float* __restrict__ h) {
    __shared__ float feat[4][64];
    int t = threadIdx.x;
    int el = t >> 6, o = t & 63;
    int e = blockIdx.x * 4 + el;
    int dst = 0;
    if (e < B_ * E_PPI_) {
        int b = e / E_PPI_, le = e % E_PPI_;
        int s = connect[le] + b * M_;
        dst   = connect[E_PPI_ + le] + b * M_;
        float v;
        if (o < 32) v = xp[dst * 32 + o];
        else        v = xp[s * 32 + (o - 32)] - xp[dst * 32 + (o - 32)];
        feat[el][o] = v;
    }
    __syncthreads();
    if (e < B_ * E_PPI_) {
        float s = b2[o];
#pragma unroll
        for (int k = 0; k < 64; k++) s += feat[el][k] * W2[k * 64 + o];
        s = fmaxf(s, 0.f);
        atomicMax((int*)&h[dst * 64 + o], __float_as_int(s));
    }
}

// ------------------------------ small kNN on pooled graphs (100 nodes) ------
// Same reference-mimicking fp32 arithmetic (sequential FMA dot, tree sq).
__global__ void knn_small_kernel(const float* __restrict__ h, int* __restrict__ knn2) {
    __shared__ float xsf[M_ * 64];
    __shared__ float sqs[M_];
    int b = blockIdx.x, t = threadIdx.x;   // 128 threads
    const float4* src4 = (const float4*)(h + (size_t)b * M_ * 64);
    float4* dst4 = (float4*)xsf;
    for (int idx = t; idx < M_ * 16; idx += 128) dst4[idx] = src4[idx];
    __syncthreads();
    if (t < M_) {
        const float* r = xsf + t * 64;
        float p[32];
#pragma unroll
        for (int q = 0; q < 32; q++) {
            float a = __fmaf_rn(r[2 * q], r[2 * q], 0.f);
            p[q] = __fmaf_rn(r[2 * q + 1], r[2 * q + 1], a);
        }
#pragma unroll
        for (int off = 16; off > 0; off >>= 1)
#pragma unroll
            for (int c = 0; c < 16; c++)
                if (c < off) p[c] = __fadd_rn(p[c], p[c + off]);
        sqs[t] = p[0];
    }
    __syncthreads();
    if (t < M_) {
        float sqi = sqs[t];
        float bd0 = 3.4e38f, bd1 = 3.4e38f, bd2 = 3.4e38f;
        int bi0 = 0, bi1 = 0, bi2 = 0;
        for (int j = 0; j < M_; j++) {
            if (j == t) continue;
            float dot = 0.f;
#pragma unroll
            for (int c = 0; c < 64; c++)
                dot = __fmaf_rn(xsf[t * 64 + c], xsf[j * 64 + c], dot);
            float t1 = __fadd_rn(sqi, sqs[j]);
            float t2 = __fmul_rn(2.f, dot);
            float d  = __fsub_rn(t1, t2);
            if (d < bd2) {
                if (d < bd0)      { bd2=bd1; bi2=bi1; bd1=bd0; bi1=bi0; bd0=d; bi0=j; }
                else if (d < bd1) { bd2=bd1; bi2=bi1; bd1=d;   bi1=j; }
                else              { bd2=d;   bi2=j; }
            }
        }
        int g = b * M_ + t;
        knn2[g * 3 + 0] = b * M_ + bi0;
        knn2[g * 3 + 1] = b * M_ + bi1;
        knn2[g * 3 + 2] = b * M_ + bi2;
    }
}

// ------------------------------ dynamic edge conv ---------------------------
// block: 2 edges x 64 out-channels (128 threads)
__global__ void dyn_conv_kernel(const float* __restrict__ h, const int* __restrict__ knn2,
                                const float* __restrict__ W3, const float* __restrict__ b3,
                                float* __restrict__ y) {
    __shared__ float feat[2][128];
    int t = threadIdx.x;
    int e0 = blockIdx.x * 2;
#pragma unroll
    for (int p = 0; p < 2; p++) {
        int e = e0 + p;
        if (e < NP_ * 3) {
            int g = e / 3;
            int src = knn2[e];
            int c = t;
            float v = (c < 64) ? h[g * 64 + c] : (h[src * 64 + (c - 64)] - h[g * 64 + (c - 64)]);
            feat[p][c] = v;
        }
    }
    __syncthreads();
    int el = t >> 6, o = t & 63;
    int e = e0 + el;
    if (e < NP_ * 3) {
        int g = e / 3;
        float s = b3[o];
#pragma unroll
        for (int k = 0; k < 128; k++) s += feat[el][k] * W3[k * 64 + o];
        s = fmaxf(s, 0.f);
        atomicMax((int*)&y[g * 64 + o], __float_as_int(s));
    }
}

// ------------------------------ final MLP (f2) ------------------------------
__global__ void final_mlp_kernel(const float* __restrict__ h, const float* __restrict__ y,
                                 const float* __restrict__ w1, const float* __restrict__ b1,
                                 const float* __restrict__ w2, const float* __restrict__ b2,
                                 const float* __restrict__ w3, const float* __restrict__ b3,
                                 float* __restrict__ out) {
    int r = blockIdx.x * blockDim.x + threadIdx.x;
    if (r >= NP_) return;
    float z[64];
#pragma unroll
    for (int c = 0; c < 64; c++) z[c] = h[r * 64 + c] + y[r * 64 + c];
    float a1[32];
#pragma unroll
    for (int o = 0; o < 32; o++) {
        float s = b1[o];
        for (int k = 0; k < 64; k++) s += z[k] * w1[k * 32 + o];
        a1[o] = selu_f(s);
    }
    float a2[16];
#pragma unroll
    for (int o = 0; o < 16; o++) {
        float s = b2[o];
        for (int k = 0; k < 32; k++) s += a1[k] * w2[k * 16 + o];
        a2[o] = selu_f(s);
    }
#pragma unroll
    for (int o = 0; o < 16; o++) {
        float s = b3[o];
        for (int k = 0; k < 16; k++) s += a2[k] * w3[k * 16 + o];
        out[r * 16 + o] = s;
    }
}

// ------------------------------ host orchestration --------------------------
template<typename T>
static T* sym_addr(const void* sym) {
    void* p = nullptr;
    cudaGetSymbolAddress(&p, sym);
    return (T*)p;
}

extern "C" void kernel_launch(void* const* d_in, const int* in_sizes, int n_in,
                              void* d_out, int out_size) {
    const float* x    = (const float*)d_in[0];
    const float* ew   = (const float*)d_in[1];
    const int*   conn = (const int*)d_in[3];
    const float* W0   = (const float*)d_in[4];
    const float* b0   = (const float*)d_in[5];
    const float* gna  = (const float*)d_in[6];
    const float* gng  = (const float*)d_in[7];
    const float* gnb  = (const float*)d_in[8];
    const float* W1   = (const float*)d_in[9];
    const float* b1c  = (const float*)d_in[10];
    const float* f1w1 = (const float*)d_in[11];
    const float* f1b1 = (const float*)d_in[12];
    const float* f1w2 = (const float*)d_in[13];
    const float* f1b2 = (const float*)d_in[14];
    const float* f1w3 = (const float*)d_in[15];
    const float* f1b3 = (const float*)d_in[16];
    const float* W2   = (const float*)d_in[17];
    const float* b2   = (const float*)d_in[18];
    const float* W3   = (const float*)d_in[19];
    const float* b3   = (const float*)d_in[20];
    const float* f2w1 = (const float*)d_in[21];
    const float* f2b1 = (const float*)d_in[22];
    const float* f2w2 = (const float*)d_in[23];
    const float* f2b2 = (const float*)d_in[24];
    const float* f2w3 = (const float*)d_in[25];
    const float* f2b3 = (const float*)d_in[26];

    float* out_u = (float*)d_out;                       // [32768, 100]
    float* out_v = out_u + (size_t)N_TOT * M_;          // [800, 16]

    float* sq   = sym_addr<float>(g_sq);
    int*   knn  = sym_addr<int>(g_knn);
    float* dn   = sym_addr<float>(g_dn);
    float* wn   = sym_addr<float>(g_wn);
    float* Z    = sym_addr<float>(g_Z);
    float* u0   = sym_addr<float>(g_u0);
    float* u1   = sym_addr<float>(g_u1);
    float* t1   = sym_addr<float>(g_t1);
    float* t2   = sym_addr<float>(g_t2);
    float* S    = sym_addr<float>(g_S);
    float* amean= sym_addr<float>(g_amean);
    float* rstd = sym_addr<float>(g_rstd);
    float* xp   = sym_addr<float>(g_xp);
    float* h    = sym_addr<float>(g_h);
    float* y    = sym_addr<float>(g_y);
    int*   knn2 = sym_addr<int>(g_knn2);

    // ---- edge normalization prerequisites (deg depends only on edge_weight)
    dn_kernel<<<(N_TOT + 255) / 256, 256>>>(ew, dn, N_TOT);

    // ---- stage 1: kNN on x (C=32)
    sqnorm32_kernel<<<N_TOT / 256, 256>>>(x, sq, N_TOT);
    knn_kernel<32><<<dim3(NG_ / 128, B_), 128>>>(x, sq, knn, NG_);
    wn_kernel<<<(3 * N_TOT + 255) / 256, 256>>>(ew, knn, dn, wn, 3 * N_TOT);

    // ---- conv0: Chebyshev terms into Z (N x 128), then one GEMM
    {
        int total = N_TOT * 8;   // N * C/4, C=32
        copy_slice_kernel<<<(total + 255) / 256, 256>>>(x, Z, 8, 32, total);
        lap_kernel<<<(total + 255) / 256, 256>>>(Z + 0,  Z,       Z + 32, 128, 8, 1.f,  0.f, knn, wn, total);
        lap_kernel<<<(total + 255) / 256, 256>>>(Z + 32, Z + 0,   Z + 64, 128, 8, 2.f, -1.f, knn, wn, total);
        lap_kernel<<<(total + 255) / 256, 256>>>(Z + 64, Z + 32,  Z + 96, 128, 8, 2.f, -1.f, knn, wn, total);
        gemm_kernel<0><<<dim3(1, N_TOT / 64), 256>>>(Z, W0, b0, u0, 128, 64);
    }

    // ---- GraphNorm
    gn_reduce_kernel<<<B_, 256>>>(u0, gna, amean, rstd);
    gn_norm_kernel<<<(N_TOT * 64) / 256, 256>>>(u0, gng, gnb, amean, rstd);

    // ---- stage 2: kNN on u0 (C=64)
    sqnorm64_kernel<<<N_TOT / 256, 256>>>(u0, sq, N_TOT);
    knn_kernel<64><<<dim3(NG_ / 128, B_), 128>>>(u0, sq, knn, NG_);
    wn_kernel<<<(3 * N_TOT + 255) / 256, 256>>>(ew, knn, dn, wn, 3 * N_TOT);

    // ---- conv1: Chebyshev into Z (N x 256), GEMM -> u1 (N x 400)
    {
        int total = N_TOT * 16;  // N * C/4, C=64
        copy_slice_kernel<<<(total + 255) / 256, 256>>>(u0, Z, 16, 64, total);
        lap_kernel<<<(total + 255) / 256, 256>>>(Z + 0,   Z,        Z + 64,  256, 16, 1.f,  0.f, knn, wn, total);
        lap_kernel<<<(total + 255) / 256, 256>>>(Z + 64,  Z + 0,    Z + 128, 256, 16, 2.f, -1.f, knn, wn, total);
        lap_kernel<<<(total + 255) / 256, 256>>>(Z + 128, Z + 64,   Z + 192, 256, 16, 2.f, -1.f, knn, wn, total);
        gemm_kernel<0><<<dim3(7, N_TOT / 64), 256>>>(Z, W1, b1c, u1, 256, 400);
    }

    // ---- fc1 MLP: 400 -> 200 -> 100 -> 100 (u written into d_out)
    gemm_kernel<1><<<dim3(4, N_TOT / 64), 256>>>(u1, f1w1, f1b1, t1, 400, 200);
    gemm_kernel<1><<<dim3(2, N_TOT / 64), 256>>>(t1, f1w2, f1b2, t2, 200, 100);
    gemm_kernel<0><<<dim3(2, N_TOT / 64), 256>>>(t2, f1w3, f1b3, out_u, 100, 100);

    // ---- DiffPool soft pooling
    softmax_kernel<<<N_TOT / 256, 256>>>(out_u, S);
    pool_kernel<<<dim3(M_, B_), 128>>>(S, x, xp);

    // ---- PPI edge conv + dynamic edge conv
    zero2_kernel<<<(NP_ * HID_ + 255) / 256, 256>>>(h, y, NP_ * HID_);
    ppi_conv_kernel<<<(B_ * E_PPI_ + 3) / 4, 256>>>(xp, conn, W2, b2, h);
    knn_small_kernel<<<B_, 128>>>(h, knn2);
    dyn_conv_kernel<<<(NP_ * 3 + 1) / 2, 128>>>(h, knn2, W3, b3, y);

    // ---- final MLP -> v
    final_mlp_kernel<<<(NP_ + 127) / 128, 128>>>(h, y, f2w1, f2b1, f2w2, f2b2,
                                                 f2w3, f2b3, out_v);
}

// round 4
// speedup vs baseline: 1.0889x; 1.0889x over previous
#include <cuda_runtime.h>
#include <math.h>
#include <stdint.h>

#define N_TOT 32768
#define B_    8
#define NG_   4096
#define KNN_  3
#define IN_CH_ 32
#define HID_  64
#define M_    100
#define OUT_CH_ 16
#define NP_   800      // B*M pooled nodes
#define E_PPI_ 600

// ------------------------------ scratch (device globals; no allocs) ---------
__device__ float g_sq[N_TOT];
__device__ int   g_knn[N_TOT * 3];
__device__ float g_dn[N_TOT];
__device__ float g_wn[N_TOT * 3];
__device__ float g_Z[(size_t)N_TOT * 256];
__device__ float g_u0[(size_t)N_TOT * 64];
__device__ float g_u1[(size_t)N_TOT * 400];
__device__ float g_t1[(size_t)N_TOT * 200];
__device__ float g_t2[(size_t)N_TOT * 100];
__device__ float g_S [(size_t)N_TOT * 100];
__device__ float g_amean[B_ * HID_];
__device__ float g_rstd [B_ * HID_];
__device__ float g_xp[NP_ * IN_CH_];
__device__ float g_h [NP_ * HID_];
__device__ float g_y [NP_ * HID_];
__device__ int   g_knn2[NP_ * 3];

// ------------------------------ helpers -------------------------------------
__device__ __forceinline__ float selu_f(float x) {
    const float sc = 1.0507009873554804934193349852946f;
    const float al = 1.6732632423543772848170429916717f;
    return x > 0.f ? sc * x : sc * al * expm1f(x);
}

// Packed fp32x2 FMA (Blackwell FFMA2). Each 32-bit lane is an independent,
// correctly-rounded fp32 FMA -> bit-identical to scalar FFMA chains.
__device__ __forceinline__ void ffma2(unsigned long long& d,
                                      unsigned long long a,
                                      unsigned long long b) {
    asm("fma.rn.f32x2 %0, %1, %2, %3;" : "=l"(d) : "l"(a), "l"(b), "l"(d));
}
__device__ __forceinline__ unsigned long long pack2(float lo, float hi) {
    unsigned long long r;
    asm("mov.b64 %0, {%1, %2};" : "=l"(r)
        : "r"(__float_as_uint(lo)), "r"(__float_as_uint(hi)));
    return r;
}
__device__ __forceinline__ void unpack2(unsigned long long v, float& lo, float& hi) {
    unsigned int a, b;
    asm("mov.b64 {%0, %1}, %2;" : "=r"(a), "=r"(b) : "l"(v));
    lo = __uint_as_float(a); hi = __uint_as_float(b);
}

__device__ __forceinline__ void ladder3(float d, int j,
                                        float& bd0, float& bd1, float& bd2,
                                        int& bi0, int& bi1, int& bi2) {
    if (d < bd2) {
        if (d < bd0)      { bd2=bd1; bi2=bi1; bd1=bd0; bi1=bi0; bd0=d; bi0=j; }
        else if (d < bd1) { bd2=bd1; bi2=bi1; bd1=d;   bi1=j; }
        else              { bd2=d;   bi2=j; }
    }
}

// ---- squared norms, mimicking XLA GPU row-reduce rounding -------------------
__global__ void sqnorm32_kernel(const float* __restrict__ x, float* __restrict__ sq, int n) {
    int i = blockIdx.x * blockDim.x + threadIdx.x;
    if (i >= n) return;
    const float* r = x + (size_t)i * 32;
    float p[32];
#pragma unroll
    for (int c = 0; c < 32; c++) p[c] = __fmul_rn(r[c], r[c]);
#pragma unroll
    for (int off = 16; off > 0; off >>= 1)
#pragma unroll
        for (int c = 0; c < 16; c++)
            if (c < off) p[c] = __fadd_rn(p[c], p[c + off]);
    sq[i] = p[0];
}

__global__ void sqnorm64_kernel(const float* __restrict__ x, float* __restrict__ sq, int n) {
    int i = blockIdx.x * blockDim.x + threadIdx.x;
    if (i >= n) return;
    const float* r = x + (size_t)i * 64;
    float p[32];
#pragma unroll
    for (int t = 0; t < 32; t++) {
        float a = __fmaf_rn(r[2 * t], r[2 * t], 0.f);
        p[t] = __fmaf_rn(r[2 * t + 1], r[2 * t + 1], a);
    }
#pragma unroll
    for (int off = 16; off > 0; off >>= 1)
#pragma unroll
        for (int c = 0; c < 16; c++)
            if (c < off) p[c] = __fadd_rn(p[c], p[c + off]);
    sq[i] = p[0];
}

// ------------------------------ kNN (k=3, per graph) ------------------------
// Packed-pair FFMA2 kernel. Two neighbors (2a, 2a+1) ride the two f32x2 lanes
// of one accumulator chain; per-lane rounding sequence is bit-identical to the
// scalar sequential ascending-c FMA chain (which matches the reference).
// Shared tile interleaved so LDS.128 yields packed operands directly:
//   xsp[a][2c + (j&1)] = x[j][c],  j = 2a + (j&1)
template<int C>
__global__ void __launch_bounds__(128) knn_kernel(
        const float* __restrict__ x, const float* __restrict__ sq,
        int* __restrict__ knn, int nper) {
    const int TJ = 128;
    int b  = blockIdx.y;
    int il = blockIdx.x * 128 + threadIdx.x;   // local node in graph
    int gi = b * nper + il;

    unsigned long long xi2[C];                 // duplicated xi
    {
        const float4* xrow = (const float4*)(x + (size_t)gi * C);
#pragma unroll
        for (int q = 0; q < C / 4; q++) {
            float4 v = xrow[q];
            xi2[4 * q + 0] = pack2(v.x, v.x);
            xi2[4 * q + 1] = pack2(v.y, v.y);
            xi2[4 * q + 2] = pack2(v.z, v.z);
            xi2[4 * q + 3] = pack2(v.w, v.w);
        }
    }
    float sqi = sq[gi];

    float bd0 = 3.4e38f, bd1 = 3.4e38f, bd2 = 3.4e38f;
    int   bi0 = 0, bi1 = 0, bi2 = 0;

    __shared__ __align__(16) float xsp[TJ / 2][2 * C];
    __shared__ float sqs[TJ];

    for (int j0 = 0; j0 < nper; j0 += TJ) {
        __syncthreads();
        for (int t = threadIdx.x; t < TJ * (C / 2); t += 128) {
            int j  = t / (C / 2);
            int c0 = (t % (C / 2)) * 2;
            float2 v = *(const float2*)(x + (size_t)(b * nper + j0 + j) * C + c0);
            int a = j >> 1, lo = j & 1;
            xsp[a][2 * c0 + lo]     = v.x;
            xsp[a][2 * c0 + 2 + lo] = v.y;
        }
        for (int t = threadIdx.x; t < TJ; t += 128) sqs[t] = sq[b * nper + j0 + t];
        __syncthreads();

#pragma unroll 2
        for (int a = 0; a < TJ / 2; a += 2) {
            const ulonglong2* p0 = (const ulonglong2*)&xsp[a][0];
            const ulonglong2* p1 = (const ulonglong2*)&xsp[a + 1][0];
            unsigned long long d0 = 0ull, d1 = 0ull;
#pragma unroll
            for (int q = 0; q < C / 2; q++) {
                ulonglong2 w0 = p0[q];
                ffma2(d0, xi2[2 * q + 0], w0.x);
                ffma2(d0, xi2[2 * q + 1], w0.y);
                ulonglong2 w1 = p1[q];
                ffma2(d1, xi2[2 * q + 0], w1.x);
                ffma2(d1, xi2[2 * q + 1], w1.y);
            }
            float f00, f01, f10, f11;
            unpack2(d0, f00, f01);
            unpack2(d1, f10, f11);
#pragma unroll
            for (int s = 0; s < 4; s++) {
                int jj = 2 * a + s;
                float dot = (s == 0) ? f00 : (s == 1) ? f01 : (s == 2) ? f10 : f11;
                float t1 = __fadd_rn(sqi, sqs[jj]);
                float t2 = __fmul_rn(2.f, dot);
                float d  = __fsub_rn(t1, t2);
                int jl = j0 + jj;
                if (jl == il) continue;
                ladder3(d, jl, bd0, bd1, bd2, bi0, bi1, bi2);
            }
        }
    }
    knn[gi * 3 + 0] = b * nper + bi0;
    knn[gi * 3 + 1] = b * nper + bi1;
    knn[gi * 3 + 2] = b * nper + bi2;
}

// ------------------------------ degree / edge normalization -----------------
__global__ void dn_kernel(const float* __restrict__ w, float* __restrict__ dn, int n) {
    int g = blockIdx.x * blockDim.x + threadIdx.x;
    if (g >= n) return;
    float d = w[3 * g] + w[3 * g + 1] + w[3 * g + 2];
    dn[g] = d > 0.f ? rsqrtf(fmaxf(d, 1e-12f)) : 0.f;
}

__global__ void wn_kernel(const float* __restrict__ w, const int* __restrict__ knn,
                          const float* __restrict__ dn, float* __restrict__ wn, int ne) {
    int e = blockIdx.x * blockDim.x + threadIdx.x;
    if (e >= ne) return;
    int g = e / 3;
    wn[e] = w[e] * dn[g] * dn[knn[e]];
}

// ------------------------------ copy into Z slice ---------------------------
__global__ void copy_slice_kernel(const float* __restrict__ src, float* __restrict__ Z,
                                  int Cq, int stride4, int total) {
    int idx = blockIdx.x * blockDim.x + threadIdx.x;
    if (idx >= total) return;
    int g = idx / Cq, q = idx % Cq;
    ((float4*)Z)[(size_t)g * stride4 + q] = ((const float4*)src)[(size_t)g * Cq + q];
}

// ------------------------------ Laplacian step -------------------------------
__global__ void lap_kernel(const float* __restrict__ Zin, const float* __restrict__ Zprev,
                           float* __restrict__ Zout, int stride, int Cq,
                           float alpha, float beta,
                           const int* __restrict__ knn, const float* __restrict__ wn,
                           int total) {
    int idx = blockIdx.x * blockDim.x + threadIdx.x;
    if (idx >= total) return;
    int g = idx / Cq, q = idx % Cq;
    int s0 = knn[3 * g], s1 = knn[3 * g + 1], s2 = knn[3 * g + 2];
    float w0 = wn[3 * g], w1 = wn[3 * g + 1], w2 = wn[3 * g + 2];
    float4 a0 = ((const float4*)(Zin + (size_t)s0 * stride))[q];
    float4 a1 = ((const float4*)(Zin + (size_t)s1 * stride))[q];
    float4 a2 = ((const float4*)(Zin + (size_t)s2 * stride))[q];
    float4 r;
    r.x = alpha * (-(w0 * a0.x + w1 * a1.x + w2 * a2.x));
    r.y = alpha * (-(w0 * a0.y + w1 * a1.y + w2 * a2.y));
    r.z = alpha * (-(w0 * a0.z + w1 * a1.z + w2 * a2.z));
    r.w = alpha * (-(w0 * a0.w + w1 * a1.w + w2 * a2.w));
    if (beta != 0.f) {
        float4 p = ((const float4*)(Zprev + (size_t)g * stride))[q];
        r.x += beta * p.x; r.y += beta * p.y; r.z += beta * p.z; r.w += beta * p.w;
    }
    ((float4*)(Zout + (size_t)g * stride))[q] = r;
}

// ------------------------------ tiled GEMM + bias + act (FFMA2) -------------
// C[M,N] = act(A[M,K] @ B[K,N] + bias), BM=BN=64, BK=16, 4x4 microtile.
// A-tile stored duplicated ({a,a} pairs) so LDS.128 yields packed operands;
// B float4 reinterprets as two packed column-pairs. Per-element accumulation
// order identical to the scalar version (bit-identical outputs).
template<int ACT>
__global__ void gemm_kernel(const float* __restrict__ A, const float* __restrict__ B,
                            const float* __restrict__ bias, float* __restrict__ C,
                            int K, int Ncols) {
    __shared__ __align__(16) float As2[16][128];  // [kk][2*i] duplicated pairs
    __shared__ __align__(16) float Bs[16][64];
    const int tid  = threadIdx.x;
    const int row0 = blockIdx.y * 64;
    const int col0 = blockIdx.x * 64;
    const int tx = tid & 15, ty = tid >> 4;
    unsigned long long acc2[4][2];
#pragma unroll
    for (int i = 0; i < 4; i++) { acc2[i][0] = 0ull; acc2[i][1] = 0ull; }

    const int lin  = tid * 4;
    const int arow = lin >> 4, acol = lin & 15;
    const int brow = lin >> 6, bcol = lin & 63;

    for (int k0 = 0; k0 < K; k0 += 16) {
        float4 av = make_float4(0.f, 0.f, 0.f, 0.f);
        if (k0 + acol < K)
            av = *(const float4*)(A + (size_t)(row0 + arow) * K + k0 + acol);
        *(float2*)&As2[acol + 0][2 * arow] = make_float2(av.x, av.x);
        *(float2*)&As2[acol + 1][2 * arow] = make_float2(av.y, av.y);
        *(float2*)&As2[acol + 2][2 * arow] = make_float2(av.z, av.z);
        *(float2*)&As2[acol + 3][2 * arow] = make_float2(av.w, av.w);

        float4 bv = make_float4(0.f, 0.f, 0.f, 0.f);
        int gk = k0 + brow, gc = col0 + bcol;
        if (gk < K && gc < Ncols)
            bv = *(const float4*)(B + (size_t)gk * Ncols + gc);
        *(float4*)&Bs[brow][bcol] = bv;
        __syncthreads();
#pragma unroll
        for (int kk = 0; kk < 16; kk++) {
            ulonglong2 a01 = *(const ulonglong2*)&As2[kk][ty * 8];
            ulonglong2 a23 = *(const ulonglong2*)&As2[kk][ty * 8 + 4];
            ulonglong2 bq  = *(const ulonglong2*)&Bs[kk][tx * 4];
            ffma2(acc2[0][0], a01.x, bq.x); ffma2(acc2[0][1], a01.x, bq.y);
            ffma2(acc2[1][0], a01.y, bq.x); ffma2(acc2[1][1], a01.y, bq.y);
            ffma2(acc2[2][0], a23.x, bq.x); ffma2(acc2[2][1], a23.x, bq.y);
            ffma2(acc2[3][0], a23.y, bq.x); ffma2(acc2[3][1], a23.y, bq.y);
        }
        __syncthreads();
    }
#pragma unroll
    for (int i = 0; i < 4; i++) {
        float a0, a1, a2, a3;
        unpack2(acc2[i][0], a0, a1);
        unpack2(acc2[i][1], a2, a3);
        float accs[4] = {a0, a1, a2, a3};
        int row = row0 + ty * 4 + i;
#pragma unroll
        for (int j = 0; j < 4; j++) {
            int col = col0 + tx * 4 + j;
            if (col < Ncols) {
                float v = accs[j] + bias[col];
                if (ACT == 1) v = selu_f(v);
                C[(size_t)row * Ncols + col] = v;
            }
        }
    }
}

// ------------------------------ GraphNorm -----------------------------------
__global__ void gn_reduce_kernel(const float* __restrict__ u, const float* __restrict__ alpha,
                                 float* __restrict__ amean, float* __restrict__ rstd) {
    int b = blockIdx.x;
    int t = threadIdx.x;               // 256
    int c = t & 63, rg = t >> 6;
    float s = 0.f;
    for (int n = rg; n < NG_; n += 4) s += u[((size_t)(b * NG_ + n)) * 64 + c];
    __shared__ float sh[256];
    sh[t] = s;
    __syncthreads();
    __shared__ float smean[64];
    if (t < 64) {
        s = sh[t] + sh[t + 64] + sh[t + 128] + sh[t + 192];
        smean[t] = s * (1.f / NG_);
    }
    __syncthreads();
    float am = alpha[c] * smean[c];
    float s2 = 0.f;
    for (int n = rg; n < NG_; n += 4) {
        float v = u[((size_t)(b * NG_ + n)) * 64 + c] - am;
        s2 += v * v;
    }
    sh[t] = s2;
    __syncthreads();
    if (t < 64) {
        s2 = sh[t] + sh[t + 64] + sh[t + 128] + sh[t + 192];
        float var = s2 * (1.f / NG_);
        amean[b * 64 + t] = alpha[t] * smean[t];
        rstd [b * 64 + t] = rsqrtf(var + 1e-5f);
    }
}

__global__ void gn_norm_kernel(float* __restrict__ u, const float* __restrict__ gamma,
                               const float* __restrict__ beta, const float* __restrict__ amean,
                               const float* __restrict__ rstd) {
    int idx = blockIdx.x * blockDim.x + threadIdx.x;
    if (idx >= N_TOT * 64) return;
    int g = idx >> 6, c = idx & 63;
    int b = g >> 12;   // /4096
    float v = u[idx];
    u[idx] = gamma[c] * (v - amean[b * 64 + c]) * rstd[b * 64 + c] + beta[c];
}

// ------------------------------ softmax rows (width 100) --------------------
__global__ void softmax_kernel(const float* __restrict__ u, float* __restrict__ S) {
    int r = blockIdx.x * blockDim.x + threadIdx.x;
    if (r >= N_TOT) return;
    const float* row = u + (size_t)r * M_;
    float* so = S + (size_t)r * M_;
    float m = -3.4e38f;
    for (int i = 0; i < M_; i++) m = fmaxf(m, row[i]);
    float s = 0.f;
    for (int i = 0; i < M_; i++) { float e = expf(row[i] - m); so[i] = e; s += e; }
    float inv = 1.f / s;
    for (int i = 0; i < M_; i++) so[i] *= inv;
}

// ------------------------------ DiffPool pooling ----------------------------
__global__ void pool_kernel(const float* __restrict__ S, const float* __restrict__ x,
                            float* __restrict__ xp) {
    int m = blockIdx.x, b = blockIdx.y;
    int t = threadIdx.x;
    float acc[32];
#pragma unroll
    for (int c = 0; c < 32; c++) acc[c] = 0.f;
    float ssum = 0.f;
    for (int n = t; n < NG_; n += 128) {
        float s = S[((size_t)(b * NG_ + n)) * M_ + m];
        ssum += s;
        const float4* xr = (const float4*)(x + (size_t)(b * NG_ + n) * 32);
#pragma unroll
        for (int q = 0; q < 8; q++) {
            float4 v = xr[q];
            acc[4 * q + 0] += s * v.x; acc[4 * q + 1] += s * v.y;
            acc[4 * q + 2] += s * v.z; acc[4 * q + 3] += s * v.w;
        }
    }
#pragma unroll
    for (int c = 0; c < 32; c++) {
        float v = acc[c];
        for (int off = 16; off > 0; off >>= 1) v += __shfl_down_sync(0xffffffffu, v, off);
        acc[c] = v;
    }
    { float v = ssum; for (int off = 16; off > 0; off >>= 1) v += __shfl_down_sync(0xffffffffu, v, off); ssum = v; }
    __shared__ float red[4][33];
    int lane = t & 31, w = t >> 5;
    if (lane == 0) { for (int c = 0; c < 32; c++) red[w][c] = acc[c]; red[w][32] = ssum; }
    __syncthreads();
    if (t < 33) { red[0][t] = red[0][t] + red[1][t] + red[2][t] + red[3][t]; }
    __syncthreads();
    if (t < 32) xp[((size_t)(b * M_ + m)) * 32 + t] = red[0][t] / red[0][32];
}

// ------------------------------ zero-init -----------------------------------
__global__ void zero2_kernel(float* a, float* b, int n) {
    int i = blockIdx.x * blockDim.x + threadIdx.x;
    if (i < n) { a[i] = 0.f; b[i] = 0.f; }
}

// ------------------------------ PPI edge conv -------------------------------
__global__ void ppi_conv_kernel(const float* __restrict__ xp, const int* __restrict__ connect,
                                const float* __restrict__ W2, const float* __restrict__ b2,
                                float* __restrict__ h) {
    __shared__ float feat[4][64];
    int t = threadIdx.x;
    int el = t >> 6, o = t & 63;
    int e = blockIdx.x * 4 + el;
    int dst = 0;
    if (e < B_ * E_PPI_) {
        int b = e / E_PPI_, le = e % E_PPI_;
        int s = connect[le] + b * M_;
        dst   = connect[E_PPI_ + le] + b * M_;
        float v;
        if (o < 32) v = xp[dst * 32 + o];
        else        v = xp[s * 32 + (o - 32)] - xp[dst * 32 + (o - 32)];
        feat[el][o] = v;
    }
    __syncthreads();
    if (e < B_ * E_PPI_) {
        float s = b2[o];
#pragma unroll
        for (int k = 0; k < 64; k++) s += feat[el][k] * W2[k * 64 + o];
        s = fmaxf(s, 0.f);
        atomicMax((int*)&h[dst * 64 + o], __float_as_int(s));
    }
}

// ------------------------------ small kNN on pooled graphs (100 nodes) ------
__global__ void knn_small_kernel(const float* __restrict__ h, int* __restrict__ knn2) {
    __shared__ float xsf[M_ * 64];
    __shared__ float sqs[M_];
    int b = blockIdx.x, t = threadIdx.x;   // 128 threads
    const float4* src4 = (const float4*)(h + (size_t)b * M_ * 64);
    float4* dst4 = (float4*)xsf;
    for (int idx = t; idx < M_ * 16; idx += 128) dst4[idx] = src4[idx];
    __syncthreads();
    if (t < M_) {
        const float* r = xsf + t * 64;
        float p[32];
#pragma unroll
        for (int q = 0; q < 32; q++) {
            float a = __fmaf_rn(r[2 * q], r[2 * q], 0.f);
            p[q] = __fmaf_rn(r[2 * q + 1], r[2 * q + 1], a);
        }
#pragma unroll
        for (int off = 16; off > 0; off >>= 1)
#pragma unroll
            for (int c = 0; c < 16; c++)
                if (c < off) p[c] = __fadd_rn(p[c], p[c + off]);
        sqs[t] = p[0];
    }
    __syncthreads();
    if (t < M_) {
        float sqi = sqs[t];
        float bd0 = 3.4e38f, bd1 = 3.4e38f, bd2 = 3.4e38f;
        int bi0 = 0, bi1 = 0, bi2 = 0;
        for (int j = 0; j < M_; j++) {
            if (j == t) continue;
            float dot = 0.f;
#pragma unroll
            for (int c = 0; c < 64; c++)
                dot = __fmaf_rn(xsf[t * 64 + c], xsf[j * 64 + c], dot);
            float t1 = __fadd_rn(sqi, sqs[j]);
            float t2 = __fmul_rn(2.f, dot);
            float d  = __fsub_rn(t1, t2);
            if (d < bd2) {
                if (d < bd0)      { bd2=bd1; bi2=bi1; bd1=bd0; bi1=bi0; bd0=d; bi0=j; }
                else if (d < bd1) { bd2=bd1; bi2=bi1; bd1=d;   bi1=j; }
                else              { bd2=d;   bi2=j; }
            }
        }
        int g = b * M_ + t;
        knn2[g * 3 + 0] = b * M_ + bi0;
        knn2[g * 3 + 1] = b * M_ + bi1;
        knn2[g * 3 + 2] = b * M_ + bi2;
    }
}

// ------------------------------ dynamic edge conv ---------------------------
__global__ void dyn_conv_kernel(const float* __restrict__ h, const int* __restrict__ knn2,
                                const float* __restrict__ W3, const float* __restrict__ b3,
                                float* __restrict__ y) {
    __shared__ float feat[2][128];
    int t = threadIdx.x;
    int e0 = blockIdx.x * 2;
#pragma unroll
    for (int p = 0; p < 2; p++) {
        int e = e0 + p;
        if (e < NP_ * 3) {
            int g = e / 3;
            int src = knn2[e];
            int c = t;
            float v = (c < 64) ? h[g * 64 + c] : (h[src * 64 + (c - 64)] - h[g * 64 + (c - 64)]);
            feat[p][c] = v;
        }
    }
    __syncthreads();
    int el = t >> 6, o = t & 63;
    int e = e0 + el;
    if (e < NP_ * 3) {
        int g = e / 3;
        float s = b3[o];
#pragma unroll
        for (int k = 0; k < 128; k++) s += feat[el][k] * W3[k * 64 + o];
        s = fmaxf(s, 0.f);
        atomicMax((int*)&y[g * 64 + o], __float_as_int(s));
    }
}

// ------------------------------ final MLP (f2) ------------------------------
__global__ void final_mlp_kernel(const float* __restrict__ h, const float* __restrict__ y,
                                 const float* __restrict__ w1, const float* __restrict__ b1,
                                 const float* __restrict__ w2, const float* __restrict__ b2,
                                 const float* __restrict__ w3, const float* __restrict__ b3,
                                 float* __restrict__ out) {
    int r = blockIdx.x * blockDim.x + threadIdx.x;
    if (r >= NP_) return;
    float z[64];
#pragma unroll
    for (int c = 0; c < 64; c++) z[c] = h[r * 64 + c] + y[r * 64 + c];
    float a1[32];
#pragma unroll
    for (int o = 0; o < 32; o++) {
        float s = b1[o];
        for (int k = 0; k < 64; k++) s += z[k] * w1[k * 32 + o];
        a1[o] = selu_f(s);
    }
    float a2[16];
#pragma unroll
    for (int o = 0; o < 16; o++) {
        float s = b2[o];
        for (int k = 0; k < 32; k++) s += a1[k] * w2[k * 16 + o];
        a2[o] = selu_f(s);
    }
#pragma unroll
    for (int o = 0; o < 16; o++) {
        float s = b3[o];
        for (int k = 0; k < 16; k++) s += a2[k] * w3[k * 16 + o];
        out[r * 16 + o] = s;
    }
}

// ------------------------------ host orchestration --------------------------
template<typename T>
static T* sym_addr(const void* sym) {
    void* p = nullptr;
    cudaGetSymbolAddress(&p, sym);
    return (T*)p;
}

extern "C" void kernel_launch(void* const* d_in, const int* in_sizes, int n_in,
                              void* d_out, int out_size) {
    const float* x    = (const float*)d_in[0];
    const float* ew   = (const float*)d_in[1];
    const int*   conn = (const int*)d_in[3];
    const float* W0   = (const float*)d_in[4];
    const float* b0   = (const float*)d_in[5];
    const float* gna  = (const float*)d_in[6];
    const float* gng  = (const float*)d_in[7];
    const float* gnb  = (const float*)d_in[8];
    const float* W1   = (const float*)d_in[9];
    const float* b1c  = (const float*)d_in[10];
    const float* f1w1 = (const float*)d_in[11];
    const float* f1b1 = (const float*)d_in[12];
    const float* f1w2 = (const float*)d_in[13];
    const float* f1b2 = (const float*)d_in[14];
    const float* f1w3 = (const float*)d_in[15];
    const float* f1b3 = (const float*)d_in[16];
    const float* W2   = (const float*)d_in[17];
    const float* b2   = (const float*)d_in[18];
    const float* W3   = (const float*)d_in[19];
    const float* b3   = (const float*)d_in[20];
    const float* f2w1 = (const float*)d_in[21];
    const float* f2b1 = (const float*)d_in[22];
    const float* f2w2 = (const float*)d_in[23];
    const float* f2b2 = (const float*)d_in[24];
    const float* f2w3 = (const float*)d_in[25];
    const float* f2b3 = (const float*)d_in[26];

    float* out_u = (float*)d_out;                       // [32768, 100]
    float* out_v = out_u + (size_t)N_TOT * M_;          // [800, 16]

    float* sq   = sym_addr<float>(g_sq);
    int*   knn  = sym_addr<int>(g_knn);
    float* dn   = sym_addr<float>(g_dn);
    float* wn   = sym_addr<float>(g_wn);
    float* Z    = sym_addr<float>(g_Z);
    float* u0   = sym_addr<float>(g_u0);
    float* u1   = sym_addr<float>(g_u1);
    float* t1   = sym_addr<float>(g_t1);
    float* t2   = sym_addr<float>(g_t2);
    float* S    = sym_addr<float>(g_S);
    float* amean= sym_addr<float>(g_amean);
    float* rstd = sym_addr<float>(g_rstd);
    float* xp   = sym_addr<float>(g_xp);
    float* h    = sym_addr<float>(g_h);
    float* y    = sym_addr<float>(g_y);
    int*   knn2 = sym_addr<int>(g_knn2);

    // ---- edge normalization prerequisites (deg depends only on edge_weight)
    dn_kernel<<<(N_TOT + 255) / 256, 256>>>(ew, dn, N_TOT);

    // ---- stage 1: kNN on x (C=32)
    sqnorm32_kernel<<<N_TOT / 256, 256>>>(x, sq, N_TOT);
    knn_kernel<32><<<dim3(NG_ / 128, B_), 128>>>(x, sq, knn, NG_);
    wn_kernel<<<(3 * N_TOT + 255) / 256, 256>>>(ew, knn, dn, wn, 3 * N_TOT);

    // ---- conv0: Chebyshev terms into Z (N x 128), then one GEMM
    {
        int total = N_TOT * 8;   // N * C/4, C=32
        copy_slice_kernel<<<(total + 255) / 256, 256>>>(x, Z, 8, 32, total);
        lap_kernel<<<(total + 255) / 256, 256>>>(Z + 0,  Z,       Z + 32, 128, 8, 1.f,  0.f, knn, wn, total);
        lap_kernel<<<(total + 255) / 256, 256>>>(Z + 32, Z + 0,   Z + 64, 128, 8, 2.f, -1.f, knn, wn, total);
        lap_kernel<<<(total + 255) / 256, 256>>>(Z + 64, Z + 32,  Z + 96, 128, 8, 2.f, -1.f, knn, wn, total);
        gemm_kernel<0><<<dim3(1, N_TOT / 64), 256>>>(Z, W0, b0, u0, 128, 64);
    }

    // ---- GraphNorm
    gn_reduce_kernel<<<B_, 256>>>(u0, gna, amean, rstd);
    gn_norm_kernel<<<(N_TOT * 64) / 256, 256>>>(u0, gng, gnb, amean, rstd);

    // ---- stage 2: kNN on u0 (C=64)
    sqnorm64_kernel<<<N_TOT / 256, 256>>>(u0, sq, N_TOT);
    knn_kernel<64><<<dim3(NG_ / 128, B_), 128>>>(u0, sq, knn, NG_);
    wn_kernel<<<(3 * N_TOT + 255) / 256, 256>>>(ew, knn, dn, wn, 3 * N_TOT);

    // ---- conv1: Chebyshev into Z (N x 256), GEMM -> u1 (N x 400)
    {
        int total = N_TOT * 16;  // N * C/4, C=64
        copy_slice_kernel<<<(total + 255) / 256, 256>>>(u0, Z, 16, 64, total);
        lap_kernel<<<(total + 255) / 256, 256>>>(Z + 0,   Z,        Z + 64,  256, 16, 1.f,  0.f, knn, wn, total);
        lap_kernel<<<(total + 255) / 256, 256>>>(Z + 64,  Z + 0,    Z + 128, 256, 16, 2.f, -1.f, knn, wn, total);
        lap_kernel<<<(total + 255) / 256, 256>>>(Z + 128, Z + 64,   Z + 192, 256, 16, 2.f, -1.f, knn, wn, total);
        gemm_kernel<0><<<dim3(7, N_TOT / 64), 256>>>(Z, W1, b1c, u1, 256, 400);
    }

    // ---- fc1 MLP: 400 -> 200 -> 100 -> 100 (u written into d_out)
    gemm_kernel<1><<<dim3(4, N_TOT / 64), 256>>>(u1, f1w1, f1b1, t1, 400, 200);
    gemm_kernel<1><<<dim3(2, N_TOT / 64), 256>>>(t1, f1w2, f1b2, t2, 200, 100);
    gemm_kernel<0><<<dim3(2, N_TOT / 64), 256>>>(t2, f1w3, f1b3, out_u, 100, 100);

    // ---- DiffPool soft pooling
    softmax_kernel<<<N_TOT / 256, 256>>>(out_u, S);
    pool_kernel<<<dim3(M_, B_), 128>>>(S, x, xp);

    // ---- PPI edge conv + dynamic edge conv
    zero2_kernel<<<(NP_ * HID_ + 255) / 256, 256>>>(h, y, NP_ * HID_);
    ppi_conv_kernel<<<(B_ * E_PPI_ + 3) / 4, 256>>>(xp, conn, W2, b2, h);
    knn_small_kernel<<<B_, 128>>>(h, knn2);
    dyn_conv_kernel<<<(NP_ * 3 + 1) / 2, 128>>>(h, knn2, W3, b3, y);

    // ---- final MLP -> v
    final_mlp_kernel<<<(NP_ + 127) / 128, 128>>>(h, y, f2w1, f2b1, f2w2, f2b2,
                                                 f2w3, f2b3, out_v);
}